// round 15
// baseline (speedup 1.0000x reference)
#include <cuda_runtime.h>
#include <cuda_fp16.h>
#include <cstdint>
#include <math.h>

#define BB 4096
#define EE 1024
#define HH 1024
#define CC 1024
#define DD 3072

// ---- scratch (device globals; allocation-rule-safe) ----
__device__ float g_preact[(size_t)BB * 4 * HH];            // [B,4H] fp32 preacts
__device__ float g_bias0 [4 * HH];
__device__ float g_bias1 [EE];
__device__ __align__(16) __half g_embH  [(size_t)BB * EE];
__device__ __align__(16) __half g_hidIH [(size_t)BB * HH];
__device__ __align__(16) __half g_ctxH  [(size_t)BB * CC];
__device__ __align__(16) __half g_WgH   [(size_t)4 * HH * DD];
__device__ __align__(16) __half g_WhH   [(size_t)EE * HH];
__device__ __align__(16) __half g_WcH   [(size_t)EE * CC];
__device__ __align__(16) __half g_WpH   [(size_t)EE * EE];
__device__ __align__(16) __half g_hidcH [(size_t)BB * HH];
__device__ __align__(16) __half g_residH[(size_t)BB * EE];

__device__ __forceinline__ uint32_t smem_u32(const void* p) {
    uint32_t a;
    asm("{ .reg .u64 t; cvta.to.shared.u64 t, %1; cvt.u32.u64 %0, t; }" : "=r"(a) : "l"(p));
    return a;
}
__device__ __forceinline__ void cp16h(uint32_t d, const __half* g) {
    asm volatile("cp.async.cg.shared.global [%0], [%1], 16;" :: "r"(d), "l"((const void*)g));
}
__device__ __forceinline__ void mma_f16(float* c, const uint32_t* a, uint32_t b0, uint32_t b1) {
    asm volatile(
        "mma.sync.aligned.m16n8k16.row.col.f32.f16.f16.f32 "
        "{%0,%1,%2,%3}, {%4,%5,%6,%7}, {%8,%9}, {%0,%1,%2,%3};"
        : "+f"(c[0]), "+f"(c[1]), "+f"(c[2]), "+f"(c[3])
        : "r"(a[0]), "r"(a[1]), "r"(a[2]), "r"(a[3]), "r"(b0), "r"(b1));
}
#define LDSM4(r, addr) \
    asm volatile("ldmatrix.sync.aligned.m8n8.x4.shared.b16 {%0,%1,%2,%3}, [%4];" \
        : "=r"((r)[0]), "=r"((r)[1]), "=r"((r)[2]), "=r"((r)[3]) : "r"(addr))

// ---------------------------------------------------------------------------
// Fused fp32 -> fp16 conversion of ALL operands in one launch.
// Segments (in 8-element units):
//   [0, 3*524288)      : emb, hid, ctx        (524288 each)
//   [.., +4*393216)    : Wi, Wf, Wo, Wg -> g_WgH contiguous
//   [.., +3*131072)    : Wh, Wc, Wp
// total8 = 3538944 -> grid 13824 x 256.
// ---------------------------------------------------------------------------
struct CvtArgs {
    const float4* srcAct[3];
    const float4* srcWg[4];
    const float4* srcWs[3];
    uint4* dstAct[3];
    uint4* dstWs[3];
    uint4* dstWg;
};

__global__ void cvt_all(CvtArgs a)
{
    const int i = blockIdx.x * blockDim.x + threadIdx.x;
    const float4* src;
    uint4* dst;
    int off;
    if (i < 3 * 524288) {
        const int seg = i / 524288; off = i - seg * 524288;
        src = a.srcAct[seg]; dst = a.dstAct[seg];
    } else if (i < 3 * 524288 + 4 * 393216) {
        const int j = i - 3 * 524288;
        const int seg = j / 393216; off = j - seg * 393216;
        src = a.srcWg[seg]; dst = a.dstWg + (size_t)seg * 393216;
    } else {
        const int j = i - (3 * 524288 + 4 * 393216);
        const int seg = j / 131072; off = j - seg * 131072;
        src = a.srcWs[seg]; dst = a.dstWs[seg];
    }
    const float4 v0 = src[2 * off], v1 = src[2 * off + 1];
    union { uint4 u; __half2 h[4]; } o;
    o.h[0] = __float22half2_rn(make_float2(v0.x, v0.y));
    o.h[1] = __float22half2_rn(make_float2(v0.z, v0.w));
    o.h[2] = __float22half2_rn(make_float2(v1.x, v1.y));
    o.h[3] = __float22half2_rn(make_float2(v1.z, v1.w));
    dst[off] = o.u;
}

__global__ void bias_prep(const float* __restrict__ bi, const float* __restrict__ bf,
                          const float* __restrict__ bo, const float* __restrict__ bg,
                          const float* __restrict__ bh, const float* __restrict__ bc)
{
    const int i = blockIdx.x * blockDim.x + threadIdx.x;
    if (i < 4096) {
        const int g = i >> 10, n = i & 1023;
        g_bias0[i] = (g == 0) ? bi[n] : (g == 1) ? bf[n] : (g == 2) ? bo[n] : bg[n];
    }
    if (i < 1024) g_bias1[i] = bh[i] + bc[i];
}

// ---------------------------------------------------------------------------
// fp16 MMA GEMM. CTA tile 128(M) x BN(N) x 32(K); NWARP warps in
// (2 x BN/64) grid, warp tile 64x64 (4 m16 x 8 n8, k16). STAGES-deep
// cp.async pipeline, ldmatrix.x4 fragments.
// smem row = 32 halves = 64B, swizzle chunk ^= (row>>1)&3.
// MODE 0: gates  A=seg(emb,hidI,ctx)  B=Wg[gate]   -> fp32 preact (ldo 4096)
// MODE 1: resid  A=seg(hidc,ctx)      B=seg(Wh,Wc) -> fp16 resid (+bias+emb)
// MODE 2: pred   A=resid              B=Wp         -> fp32 pred
// ---------------------------------------------------------------------------
template<int MODE, int KD, int BN, int NWARP, int STAGES, int MAXCTA>
__global__ __launch_bounds__(NWARP * 32, MAXCTA)
void hgemm(const __half* __restrict__ A0, const __half* __restrict__ A1,
           const __half* __restrict__ A2,
           const __half* __restrict__ W0, const __half* __restrict__ W1,
           const float* __restrict__ bias, const float* __restrict__ addend,
           float* __restrict__ outF, __half* __restrict__ outH, int ldo)
{
    extern __shared__ __align__(1024) char smc[];
    const uint32_t sb = smem_u32(smc);
    constexpr int THREADS = NWARP * 32;
    constexpr int WNW = BN / 64;               // warps along N
    constexpr int STAGEB = (128 + BN) * 64;    // bytes per stage
    constexpr int nK = KD / 32;
    const int tid = threadIdx.x;
    const int w = tid >> 5, lane = tid & 31;
    const int wm = w / WNW, wn = w % WNW;
    const int grp = lane >> 2, tig = lane & 3;
    const int m0 = blockIdx.y * 128;
    const int n0 = blockIdx.x * BN;

    const __half* Wsel = W0;
    if (MODE == 0) Wsel = W0 + (size_t)(n0 >> 10) * 1024 * DD;
    const int nloc0 = n0 & 1023;

    float acc[4][8][4];
#pragma unroll
    for (int i = 0; i < 4; i++)
#pragma unroll
        for (int j = 0; j < 8; j++)
#pragma unroll
            for (int v = 0; v < 4; v++) acc[i][j][v] = 0.0f;

    // per-lane ldmatrix relative addresses
    uint32_t relA, relB;
    {
        const int mat = lane >> 3;
        const int ar  = wm * 64 + (lane & 7) + (mat & 1) * 8;   // + mi*16
        const int akh = mat >> 1;
        const uint32_t sw = (ar >> 1) & 3;
        relA = ar * 64 + ((((sw >> 1) << 1) | (akh ^ (sw & 1))) << 4);
        const int br  = wn * 64 + (lane & 7) + (mat >> 1) * 8;  // + njp*16
        const int bkh = mat & 1;
        const uint32_t swb = (br >> 1) & 3;
        relB = 8192 + br * 64 + ((((swb >> 1) << 1) | (bkh ^ (swb & 1))) << 4);
    }

    auto stage = [&](int kt) {
        const uint32_t base = sb + (kt % STAGES) * STAGEB;
        const int kb = kt * 32;
#pragma unroll
        for (int j = 0; j < 512 / THREADS; j++) {        // A: 128 rows x 4 chunks
            const int i = tid + j * THREADS;
            const int row = i >> 2, c = i & 3;
            const uint32_t d = base + row * 64 + ((c ^ ((row >> 1) & 3)) << 4);
            const __half* gp;
            if (MODE == 0) {
                const int seg = kb >> 10;
                const __half* s0 = (seg == 0) ? A0 : (seg == 1) ? A1 : A2;
                gp = s0 + (size_t)(m0 + row) * 1024 + (kb & 1023) + c * 8;
            } else if (MODE == 1) {
                const __half* s0 = (kb >> 10) ? A1 : A0;
                gp = s0 + (size_t)(m0 + row) * 1024 + (kb & 1023) + c * 8;
            } else {
                gp = A0 + (size_t)(m0 + row) * 1024 + kb + c * 8;
            }
            cp16h(d, gp);
        }
#pragma unroll
        for (int j = 0; j < BN * 4 / THREADS; j++) {     // B: BN rows x 4 chunks
            const int i = tid + j * THREADS;
            const int row = i >> 2, c = i & 3;
            const uint32_t d = base + 8192 + row * 64 + ((c ^ ((row >> 1) & 3)) << 4);
            const __half* gp;
            if (MODE == 0) {
                gp = Wsel + (size_t)(nloc0 + row) * DD + kb + c * 8;
            } else if (MODE == 1) {
                const __half* s0 = (kb >> 10) ? W1 : W0;
                gp = s0 + (size_t)(n0 + row) * 1024 + (kb & 1023) + c * 8;
            } else {
                gp = W0 + (size_t)(n0 + row) * 1024 + kb + c * 8;
            }
            cp16h(d, gp);
        }
        asm volatile("cp.async.commit_group;" ::: "memory");
    };

#pragma unroll
    for (int s = 0; s < STAGES - 1; s++) stage(s);

    for (int kt = 0; kt < nK; kt++) {
        asm volatile("cp.async.wait_group %0;" :: "n"(STAGES - 2) : "memory");
        __syncthreads();
        const uint32_t stg = sb + (kt % STAGES) * STAGEB;
        if (kt + STAGES - 1 < nK) stage(kt + STAGES - 1);

#pragma unroll
        for (int s = 0; s < 2; s++) {
            const uint32_t sx = s << 5;
            uint32_t a[4][4];
#pragma unroll
            for (int mi = 0; mi < 4; mi++)
                LDSM4(a[mi], stg + ((relA + mi * 1024) ^ sx));
            uint32_t b[4][4];
#pragma unroll
            for (int njp = 0; njp < 4; njp++)
                LDSM4(b[njp], stg + ((relB + njp * 1024) ^ sx));
#pragma unroll
            for (int njp = 0; njp < 4; njp++)
#pragma unroll
                for (int mi = 0; mi < 4; mi++) {
                    mma_f16(acc[mi][2 * njp],     a[mi], b[njp][0], b[njp][1]);
                    mma_f16(acc[mi][2 * njp + 1], a[mi], b[njp][2], b[njp][3]);
                }
        }
        __syncthreads();
    }

    // ---- epilogue ----
    const int gc = tig * 2;
#pragma unroll
    for (int mi = 0; mi < 4; mi++) {
        const int gm = m0 + wm * 64 + mi * 16 + grp;
#pragma unroll
        for (int nj = 0; nj < 8; nj++) {
            const int gn = n0 + wn * 64 + nj * 8 + gc;
            const float bv0 = bias[gn], bv1 = bias[gn + 1];
            float2 r0 = make_float2(acc[mi][nj][0] + bv0, acc[mi][nj][1] + bv1);
            float2 r1 = make_float2(acc[mi][nj][2] + bv0, acc[mi][nj][3] + bv1);
            if (MODE == 1) {
                const float2 d0 = *reinterpret_cast<const float2*>(
                    addend + (size_t)gm * 1024 + gn);
                const float2 d1 = *reinterpret_cast<const float2*>(
                    addend + (size_t)(gm + 8) * 1024 + gn);
                r0.x += d0.x; r0.y += d0.y; r1.x += d1.x; r1.y += d1.y;
                *reinterpret_cast<__half2*>(outH + (size_t)gm * 1024 + gn) =
                    __float22half2_rn(r0);
                *reinterpret_cast<__half2*>(outH + (size_t)(gm + 8) * 1024 + gn) =
                    __float22half2_rn(r1);
            } else {
                *reinterpret_cast<float2*>(outF + (size_t)gm * ldo + gn)       = r0;
                *reinterpret_cast<float2*>(outF + (size_t)(gm + 8) * ldo + gn) = r1;
            }
        }
    }
}

// ---------------------------------------------------------------------------
// Elementwise LSTM cell; fp32 hidden/cell to output, fp16 hidden to g_hidcH.
// ---------------------------------------------------------------------------
__device__ __forceinline__ float sigf(float x) { return 1.0f / (1.0f + __expf(-x)); }
__device__ __forceinline__ float tanhfast(float x) { return 2.0f * sigf(2.0f * x) - 1.0f; }

__global__ void lstm_elem(const float4* __restrict__ pre,
                          const float4* __restrict__ cprev,
                          float4* __restrict__ hidden,
                          float4* __restrict__ cell)
{
    const int idx = blockIdx.x * blockDim.x + threadIdx.x;
    const int b  = idx >> 8;
    const int h4 = idx & 255;
    const size_t base = (size_t)b * 1024;
    const float4 pi = pre[base + h4];
    const float4 pf = pre[base + 256 + h4];
    const float4 po = pre[base + 512 + h4];
    const float4 pg = pre[base + 768 + h4];
    const float4 cp = cprev[idx];

    const float c0 = sigf(pf.x) * cp.x + sigf(pi.x) * tanhfast(pg.x);
    const float c1 = sigf(pf.y) * cp.y + sigf(pi.y) * tanhfast(pg.y);
    const float c2 = sigf(pf.z) * cp.z + sigf(pi.z) * tanhfast(pg.z);
    const float c3 = sigf(pf.w) * cp.w + sigf(pi.w) * tanhfast(pg.w);

    const float h0 = sigf(po.x) * tanhfast(c0);
    const float h1 = sigf(po.y) * tanhfast(c1);
    const float h2 = sigf(po.z) * tanhfast(c2);
    const float h3 = sigf(po.w) * tanhfast(c3);

    cell[idx]   = make_float4(c0, c1, c2, c3);
    hidden[idx] = make_float4(h0, h1, h2, h3);

    __half2* hh = reinterpret_cast<__half2*>(g_hidcH);
    hh[idx * 2]     = __float22half2_rn(make_float2(h0, h1));
    hh[idx * 2 + 1] = __float22half2_rn(make_float2(h2, h3));
}

// ---------------------------------------------------------------------------
extern "C" void kernel_launch(void* const* d_in, const int* in_sizes, int n_in,
                              void* d_out, int out_size)
{
    (void)in_sizes; (void)n_in; (void)out_size;

    const float* emb = (const float*)d_in[0];
    const float* hid = (const float*)d_in[1];
    const float* cpr = (const float*)d_in[2];
    const float* ctx = (const float*)d_in[3];
    const float* Wi  = (const float*)d_in[4];  const float* bi = (const float*)d_in[5];
    const float* Wf  = (const float*)d_in[6];  const float* bf = (const float*)d_in[7];
    const float* Wo  = (const float*)d_in[8];  const float* bo = (const float*)d_in[9];
    const float* Wg  = (const float*)d_in[10]; const float* bg = (const float*)d_in[11];
    const float* Wc  = (const float*)d_in[12]; const float* bc = (const float*)d_in[13];
    const float* Wh  = (const float*)d_in[14]; const float* bh = (const float*)d_in[15];
    const float* Wp  = (const float*)d_in[16]; const float* bp = (const float*)d_in[17];

    float* out     = (float*)d_out;
    float* pred    = out;
    float* hiddenO = out + (size_t)BB * EE;
    float* cellO   = hiddenO + (size_t)BB * HH;

    float *preP, *b0P, *b1P;
    __half *embH, *hidIH, *ctxH, *WgHp, *WhHp, *WcHp, *WpHp, *hidcH, *residH;
    cudaGetSymbolAddress((void**)&preP,   g_preact);
    cudaGetSymbolAddress((void**)&b0P,    g_bias0);
    cudaGetSymbolAddress((void**)&b1P,    g_bias1);
    cudaGetSymbolAddress((void**)&embH,   g_embH);
    cudaGetSymbolAddress((void**)&hidIH,  g_hidIH);
    cudaGetSymbolAddress((void**)&ctxH,   g_ctxH);
    cudaGetSymbolAddress((void**)&WgHp,   g_WgH);
    cudaGetSymbolAddress((void**)&WhHp,   g_WhH);
    cudaGetSymbolAddress((void**)&WcHp,   g_WcH);
    cudaGetSymbolAddress((void**)&WpHp,   g_WpH);
    cudaGetSymbolAddress((void**)&hidcH,  g_hidcH);
    cudaGetSymbolAddress((void**)&residH, g_residH);

    // ---- fused fp16 conversion (single launch) ----
    CvtArgs ca;
    ca.srcAct[0] = (const float4*)emb;  ca.dstAct[0] = (uint4*)embH;
    ca.srcAct[1] = (const float4*)hid;  ca.dstAct[1] = (uint4*)hidIH;
    ca.srcAct[2] = (const float4*)ctx;  ca.dstAct[2] = (uint4*)ctxH;
    ca.srcWg[0] = (const float4*)Wi;  ca.srcWg[1] = (const float4*)Wf;
    ca.srcWg[2] = (const float4*)Wo;  ca.srcWg[3] = (const float4*)Wg;
    ca.dstWg = (uint4*)WgHp;
    ca.srcWs[0] = (const float4*)Wh;  ca.dstWs[0] = (uint4*)WhHp;
    ca.srcWs[1] = (const float4*)Wc;  ca.dstWs[1] = (uint4*)WcHp;
    ca.srcWs[2] = (const float4*)Wp;  ca.dstWs[2] = (uint4*)WpHp;
    cvt_all<<<13824, 256>>>(ca);
    bias_prep<<<16, 256>>>(bi, bf, bo, bg, bh, bc);

    // GEMM configs:
    //  gates: BN=256, 8 warps, 4 stages, 1 CTA/SM  (smem 4*24576 = 98304)
    //  small: BN=128, 4 warps, 4 stages, 2 CTA/SM  (smem 4*16384 = 65536)
    const int SMEM_G = 4 * 24576;
    const int SMEM_S = 4 * 16384;
    cudaFuncSetAttribute((const void*)hgemm<0, DD,   256, 8, 4, 1>,
                         cudaFuncAttributeMaxDynamicSharedMemorySize, SMEM_G);
    cudaFuncSetAttribute((const void*)hgemm<1, 2048, 128, 4, 4, 2>,
                         cudaFuncAttributeMaxDynamicSharedMemorySize, SMEM_S);
    cudaFuncSetAttribute((const void*)hgemm<2, 1024, 128, 4, 4, 2>,
                         cudaFuncAttributeMaxDynamicSharedMemorySize, SMEM_S);

    // 1) gates preact [B,4H]
    hgemm<0, DD, 256, 8, 4, 1><<<dim3(16, 32), 256, SMEM_G>>>(
        embH, hidIH, ctxH, WgHp, nullptr, b0P, nullptr, preP, nullptr, 4 * HH);

    // 2) cell update
    lstm_elem<<<4096, 256>>>((const float4*)preP, (const float4*)cpr,
                             (float4*)hiddenO, (float4*)cellO);

    // 3) resid (fp16) = emb + hidden@Wh^T + ctx@Wc^T + bh+bc
    hgemm<1, 2048, 128, 4, 4, 2><<<dim3(8, 32), 128, SMEM_S>>>(
        hidcH, ctxH, nullptr, WhHp, WcHp, b1P, emb, nullptr, residH, EE);

    // 4) prediction = resid @ Wp^T + bp
    hgemm<2, 1024, 128, 4, 4, 2><<<dim3(8, 32), 128, SMEM_S>>>(
        residH, nullptr, nullptr, WpHp, nullptr, bp, nullptr, pred, nullptr, EE);
}

// round 17
// speedup vs baseline: 1.2500x; 1.2500x over previous
#include <cuda_runtime.h>
#include <cuda_fp16.h>
#include <cstdint>
#include <math.h>

#define BB 4096
#define EE 1024
#define HH 1024
#define CC 1024
#define DD 3072

// ---- scratch (device globals; allocation-rule-safe) ----
__device__ float g_preact[(size_t)BB * 4 * HH];            // [B,4H] fp32 preacts
__device__ float g_bias0 [4 * HH];
__device__ float g_bias1 [EE];
__device__ __align__(16) __half g_embH  [(size_t)BB * EE];
__device__ __align__(16) __half g_hidIH [(size_t)BB * HH];
__device__ __align__(16) __half g_ctxH  [(size_t)BB * CC];
__device__ __align__(16) __half g_WgH   [(size_t)4 * HH * DD];
__device__ __align__(16) __half g_WhH   [(size_t)EE * HH];
__device__ __align__(16) __half g_WcH   [(size_t)EE * CC];
__device__ __align__(16) __half g_WpH   [(size_t)EE * EE];
__device__ __align__(16) __half g_hidcH [(size_t)BB * HH];
__device__ __align__(16) __half g_residH[(size_t)BB * EE];

__device__ __forceinline__ uint32_t smem_u32(const void* p) {
    uint32_t a;
    asm("{ .reg .u64 t; cvta.to.shared.u64 t, %1; cvt.u32.u64 %0, t; }" : "=r"(a) : "l"(p));
    return a;
}
__device__ __forceinline__ void cp16h(uint32_t d, const __half* g) {
    asm volatile("cp.async.cg.shared.global [%0], [%1], 16;" :: "r"(d), "l"((const void*)g));
}
__device__ __forceinline__ void mma_f16(float* c, const uint32_t* a, uint32_t b0, uint32_t b1) {
    asm volatile(
        "mma.sync.aligned.m16n8k16.row.col.f32.f16.f16.f32 "
        "{%0,%1,%2,%3}, {%4,%5,%6,%7}, {%8,%9}, {%0,%1,%2,%3};"
        : "+f"(c[0]), "+f"(c[1]), "+f"(c[2]), "+f"(c[3])
        : "r"(a[0]), "r"(a[1]), "r"(a[2]), "r"(a[3]), "r"(b0), "r"(b1));
}
#define LDSM4(r, addr) \
    asm volatile("ldmatrix.sync.aligned.m8n8.x4.shared.b16 {%0,%1,%2,%3}, [%4];" \
        : "=r"((r)[0]), "=r"((r)[1]), "=r"((r)[2]), "=r"((r)[3]) : "r"(addr))

// ---------------------------------------------------------------------------
// Fused fp32 -> fp16 conversion of ALL operands in one launch (R15-proven).
// ---------------------------------------------------------------------------
struct CvtArgs {
    const float4* srcAct[3];
    const float4* srcWg[4];
    const float4* srcWs[3];
    uint4* dstAct[3];
    uint4* dstWs[3];
    uint4* dstWg;
};

__global__ void cvt_all(CvtArgs a)
{
    const int i = blockIdx.x * blockDim.x + threadIdx.x;
    const float4* src;
    uint4* dst;
    int off;
    if (i < 3 * 524288) {
        const int seg = i / 524288; off = i - seg * 524288;
        src = a.srcAct[seg]; dst = a.dstAct[seg];
    } else if (i < 3 * 524288 + 4 * 393216) {
        const int j = i - 3 * 524288;
        const int seg = j / 393216; off = j - seg * 393216;
        src = a.srcWg[seg]; dst = a.dstWg + (size_t)seg * 393216;
    } else {
        const int j = i - (3 * 524288 + 4 * 393216);
        const int seg = j / 131072; off = j - seg * 131072;
        src = a.srcWs[seg]; dst = a.dstWs[seg];
    }
    const float4 v0 = src[2 * off], v1 = src[2 * off + 1];
    union { uint4 u; __half2 h[4]; } o;
    o.h[0] = __float22half2_rn(make_float2(v0.x, v0.y));
    o.h[1] = __float22half2_rn(make_float2(v0.z, v0.w));
    o.h[2] = __float22half2_rn(make_float2(v1.x, v1.y));
    o.h[3] = __float22half2_rn(make_float2(v1.z, v1.w));
    dst[off] = o.u;
}

__global__ void bias_prep(const float* __restrict__ bi, const float* __restrict__ bf,
                          const float* __restrict__ bo, const float* __restrict__ bg,
                          const float* __restrict__ bh, const float* __restrict__ bc)
{
    const int i = blockIdx.x * blockDim.x + threadIdx.x;
    if (i < 4096) {
        const int g = i >> 10, n = i & 1023;
        g_bias0[i] = (g == 0) ? bi[n] : (g == 1) ? bf[n] : (g == 2) ? bo[n] : bg[n];
    }
    if (i < 1024) g_bias1[i] = bh[i] + bc[i];
}

// ---------------------------------------------------------------------------
// fp16 MMA GEMM (R11-proven config).  CTA tile 128x128x32, 128 threads =
// 4 warps (2Mx2N), warp tile 64x64 (4 m16 x 8 n8, k16).  3-stage cp.async,
// ldmatrix.x4 fragments.  2 CTAs/SM.
// smem row = 32 halves = 64B, 4 chunks of 16B, swizzle chunk ^= (row>>1)&3.
// MODE 0: gates  A=seg(emb,hidI,ctx)   B=Wg[gate]  out fp32 preact (ldo 4096)
// MODE 1: resid  A=seg(hidc,ctx)       B=seg(Wh,Wc) out fp16 resid (+bias+emb)
// MODE 2: pred   A=resid               B=Wp         out fp32 pred
// ---------------------------------------------------------------------------
template<int MODE, int KD>
__global__ __launch_bounds__(128, 2)
void hgemm(const __half* __restrict__ A0, const __half* __restrict__ A1,
           const __half* __restrict__ A2,
           const __half* __restrict__ W0, const __half* __restrict__ W1,
           const float* __restrict__ bias, const float* __restrict__ addend,
           float* __restrict__ outF, __half* __restrict__ outH, int ldo)
{
    extern __shared__ __align__(1024) char smc[];
    const uint32_t sb = smem_u32(smc);
    const int tid = threadIdx.x;
    const int w = tid >> 5, lane = tid & 31;
    const int wm = w >> 1, wn = w & 1;
    const int grp = lane >> 2, tig = lane & 3;
    const int m0 = blockIdx.y * 128;
    const int n0 = blockIdx.x * 128;
    constexpr int nK = KD / 32;

    const __half* Wsel = W0;
    if (MODE == 0) Wsel = W0 + (size_t)(n0 >> 10) * 1024 * DD;
    const int nloc0 = n0 & 1023;

    float acc[4][8][4];
#pragma unroll
    for (int i = 0; i < 4; i++)
#pragma unroll
        for (int j = 0; j < 8; j++)
#pragma unroll
            for (int v = 0; v < 4; v++) acc[i][j][v] = 0.0f;

    // per-lane ldmatrix relative addresses
    uint32_t relA, relB;
    {
        const int mat = lane >> 3;
        const int ar  = wm * 64 + (lane & 7) + (mat & 1) * 8;   // + mi*16
        const int akh = mat >> 1;
        const uint32_t sw = (ar >> 1) & 3;
        relA = ar * 64 + ((((sw >> 1) << 1) | (akh ^ (sw & 1))) << 4);
        const int br  = wn * 64 + (lane & 7) + (mat >> 1) * 8;  // + njp*16
        const int bkh = mat & 1;
        const uint32_t swb = (br >> 1) & 3;
        relB = 8192 + br * 64 + ((((swb >> 1) << 1) | (bkh ^ (swb & 1))) << 4);
    }

    auto stage = [&](int kt) {
        const uint32_t base = sb + (kt % 3) * 16384;
        const int kb = kt * 32;
#pragma unroll
        for (int j = 0; j < 4; j++) {                 // A: 128 rows x 4 chunks
            const int i = tid + j * 128;
            const int row = i >> 2, c = i & 3;
            const uint32_t d = base + row * 64 + ((c ^ ((row >> 1) & 3)) << 4);
            const __half* gp;
            if (MODE == 0) {
                const int seg = kb >> 10;
                const __half* s0 = (seg == 0) ? A0 : (seg == 1) ? A1 : A2;
                gp = s0 + (size_t)(m0 + row) * 1024 + (kb & 1023) + c * 8;
            } else if (MODE == 1) {
                const __half* s0 = (kb >> 10) ? A1 : A0;
                gp = s0 + (size_t)(m0 + row) * 1024 + (kb & 1023) + c * 8;
            } else {
                gp = A0 + (size_t)(m0 + row) * 1024 + kb + c * 8;
            }
            cp16h(d, gp);
        }
#pragma unroll
        for (int j = 0; j < 4; j++) {                 // B: 128 rows x 4 chunks
            const int i = tid + j * 128;
            const int row = i >> 2, c = i & 3;
            const uint32_t d = base + 8192 + row * 64 + ((c ^ ((row >> 1) & 3)) << 4);
            const __half* gp;
            if (MODE == 0) {
                gp = Wsel + (size_t)(nloc0 + row) * DD + kb + c * 8;
            } else if (MODE == 1) {
                const __half* s0 = (kb >> 10) ? W1 : W0;
                gp = s0 + (size_t)(n0 + row) * 1024 + (kb & 1023) + c * 8;
            } else {
                gp = W0 + (size_t)(n0 + row) * 1024 + kb + c * 8;
            }
            cp16h(d, gp);
        }
        asm volatile("cp.async.commit_group;" ::: "memory");
    };

    stage(0);
    stage(1);

    for (int kt = 0; kt < nK; kt++) {
        asm volatile("cp.async.wait_group 1;" ::: "memory");
        __syncthreads();
        const uint32_t stg = sb + (kt % 3) * 16384;
        if (kt + 2 < nK) stage(kt + 2);

#pragma unroll
        for (int s = 0; s < 2; s++) {
            const uint32_t sx = s << 5;
            uint32_t a[4][4];
#pragma unroll
            for (int mi = 0; mi < 4; mi++)
                LDSM4(a[mi], stg + ((relA + mi * 1024) ^ sx));
            uint32_t b[4][4];
#pragma unroll
            for (int njp = 0; njp < 4; njp++)
                LDSM4(b[njp], stg + ((relB + njp * 1024) ^ sx));
#pragma unroll
            for (int njp = 0; njp < 4; njp++)
#pragma unroll
                for (int mi = 0; mi < 4; mi++) {
                    mma_f16(acc[mi][2 * njp],     a[mi], b[njp][0], b[njp][1]);
                    mma_f16(acc[mi][2 * njp + 1], a[mi], b[njp][2], b[njp][3]);
                }
        }
        __syncthreads();
    }

    // ---- epilogue ----
    const int gc = tig * 2;
#pragma unroll
    for (int mi = 0; mi < 4; mi++) {
        const int gm = m0 + wm * 64 + mi * 16 + grp;
#pragma unroll
        for (int nj = 0; nj < 8; nj++) {
            const int gn = n0 + wn * 64 + nj * 8 + gc;
            const float bv0 = bias[gn], bv1 = bias[gn + 1];
            float2 r0 = make_float2(acc[mi][nj][0] + bv0, acc[mi][nj][1] + bv1);
            float2 r1 = make_float2(acc[mi][nj][2] + bv0, acc[mi][nj][3] + bv1);
            if (MODE == 1) {
                const float2 d0 = *reinterpret_cast<const float2*>(
                    addend + (size_t)gm * 1024 + gn);
                const float2 d1 = *reinterpret_cast<const float2*>(
                    addend + (size_t)(gm + 8) * 1024 + gn);
                r0.x += d0.x; r0.y += d0.y; r1.x += d1.x; r1.y += d1.y;
                *reinterpret_cast<__half2*>(outH + (size_t)gm * 1024 + gn) =
                    __float22half2_rn(r0);
                *reinterpret_cast<__half2*>(outH + (size_t)(gm + 8) * 1024 + gn) =
                    __float22half2_rn(r1);
            } else {
                *reinterpret_cast<float2*>(outF + (size_t)gm * ldo + gn)       = r0;
                *reinterpret_cast<float2*>(outF + (size_t)(gm + 8) * ldo + gn) = r1;
            }
        }
    }
}

// ---------------------------------------------------------------------------
// Elementwise LSTM cell; fp32 hidden/cell to output, fp16 hidden to g_hidcH.
// ---------------------------------------------------------------------------
__device__ __forceinline__ float sigf(float x) { return 1.0f / (1.0f + __expf(-x)); }
__device__ __forceinline__ float tanhfast(float x) { return 2.0f * sigf(2.0f * x) - 1.0f; }

__global__ void lstm_elem(const float4* __restrict__ pre,
                          const float4* __restrict__ cprev,
                          float4* __restrict__ hidden,
                          float4* __restrict__ cell)
{
    const int idx = blockIdx.x * blockDim.x + threadIdx.x;
    const int b  = idx >> 8;
    const int h4 = idx & 255;
    const size_t base = (size_t)b * 1024;
    const float4 pi = pre[base + h4];
    const float4 pf = pre[base + 256 + h4];
    const float4 po = pre[base + 512 + h4];
    const float4 pg = pre[base + 768 + h4];
    const float4 cp = cprev[idx];

    const float c0 = sigf(pf.x) * cp.x + sigf(pi.x) * tanhfast(pg.x);
    const float c1 = sigf(pf.y) * cp.y + sigf(pi.y) * tanhfast(pg.y);
    const float c2 = sigf(pf.z) * cp.z + sigf(pi.z) * tanhfast(pg.z);
    const float c3 = sigf(pf.w) * cp.w + sigf(pi.w) * tanhfast(pg.w);

    const float h0 = sigf(po.x) * tanhfast(c0);
    const float h1 = sigf(po.y) * tanhfast(c1);
    const float h2 = sigf(po.z) * tanhfast(c2);
    const float h3 = sigf(po.w) * tanhfast(c3);

    cell[idx]   = make_float4(c0, c1, c2, c3);
    hidden[idx] = make_float4(h0, h1, h2, h3);

    __half2* hh = reinterpret_cast<__half2*>(g_hidcH);
    hh[idx * 2]     = __float22half2_rn(make_float2(h0, h1));
    hh[idx * 2 + 1] = __float22half2_rn(make_float2(h2, h3));
}

// ---------------------------------------------------------------------------
extern "C" void kernel_launch(void* const* d_in, const int* in_sizes, int n_in,
                              void* d_out, int out_size)
{
    (void)in_sizes; (void)n_in; (void)out_size;

    const float* emb = (const float*)d_in[0];
    const float* hid = (const float*)d_in[1];
    const float* cpr = (const float*)d_in[2];
    const float* ctx = (const float*)d_in[3];
    const float* Wi  = (const float*)d_in[4];  const float* bi = (const float*)d_in[5];
    const float* Wf  = (const float*)d_in[6];  const float* bf = (const float*)d_in[7];
    const float* Wo  = (const float*)d_in[8];  const float* bo = (const float*)d_in[9];
    const float* Wg  = (const float*)d_in[10]; const float* bg = (const float*)d_in[11];
    const float* Wc  = (const float*)d_in[12]; const float* bc = (const float*)d_in[13];
    const float* Wh  = (const float*)d_in[14]; const float* bh = (const float*)d_in[15];
    const float* Wp  = (const float*)d_in[16]; const float* bp = (const float*)d_in[17];

    float* out     = (float*)d_out;
    float* pred    = out;
    float* hiddenO = out + (size_t)BB * EE;
    float* cellO   = hiddenO + (size_t)BB * HH;

    float *preP, *b0P, *b1P;
    __half *embH, *hidIH, *ctxH, *WgHp, *WhHp, *WcHp, *WpHp, *hidcH, *residH;
    cudaGetSymbolAddress((void**)&preP,   g_preact);
    cudaGetSymbolAddress((void**)&b0P,    g_bias0);
    cudaGetSymbolAddress((void**)&b1P,    g_bias1);
    cudaGetSymbolAddress((void**)&embH,   g_embH);
    cudaGetSymbolAddress((void**)&hidIH,  g_hidIH);
    cudaGetSymbolAddress((void**)&ctxH,   g_ctxH);
    cudaGetSymbolAddress((void**)&WgHp,   g_WgH);
    cudaGetSymbolAddress((void**)&WhHp,   g_WhH);
    cudaGetSymbolAddress((void**)&WcHp,   g_WcH);
    cudaGetSymbolAddress((void**)&WpHp,   g_WpH);
    cudaGetSymbolAddress((void**)&hidcH,  g_hidcH);
    cudaGetSymbolAddress((void**)&residH, g_residH);

    // ---- fused fp16 conversion (single launch; R15-proven) ----
    CvtArgs ca;
    ca.srcAct[0] = (const float4*)emb;  ca.dstAct[0] = (uint4*)embH;
    ca.srcAct[1] = (const float4*)hid;  ca.dstAct[1] = (uint4*)hidIH;
    ca.srcAct[2] = (const float4*)ctx;  ca.dstAct[2] = (uint4*)ctxH;
    ca.srcWg[0] = (const float4*)Wi;  ca.srcWg[1] = (const float4*)Wf;
    ca.srcWg[2] = (const float4*)Wo;  ca.srcWg[3] = (const float4*)Wg;
    ca.dstWg = (uint4*)WgHp;
    ca.srcWs[0] = (const float4*)Wh;  ca.dstWs[0] = (uint4*)WhHp;
    ca.srcWs[1] = (const float4*)Wc;  ca.dstWs[1] = (uint4*)WcHp;
    ca.srcWs[2] = (const float4*)Wp;  ca.dstWs[2] = (uint4*)WpHp;
    cvt_all<<<13824, 256>>>(ca);
    bias_prep<<<16, 256>>>(bi, bf, bo, bg, bh, bc);

    const int SMEM = 3 * 16384;   // 48KB -> 2 CTAs/SM (R11-proven)
    cudaFuncSetAttribute(hgemm<0, DD>,   cudaFuncAttributeMaxDynamicSharedMemorySize, SMEM);
    cudaFuncSetAttribute(hgemm<1, 2048>, cudaFuncAttributeMaxDynamicSharedMemorySize, SMEM);
    cudaFuncSetAttribute(hgemm<2, 1024>, cudaFuncAttributeMaxDynamicSharedMemorySize, SMEM);

    // 1) gates preact [B,4H]
    hgemm<0, DD><<<dim3(32, 32), 128, SMEM>>>(
        embH, hidIH, ctxH, WgHp, nullptr, b0P, nullptr, preP, nullptr, 4 * HH);

    // 2) cell update
    lstm_elem<<<4096, 256>>>((const float4*)preP, (const float4*)cpr,
                             (float4*)hiddenO, (float4*)cellO);

    // 3) resid (fp16) = emb + hidden@Wh^T + ctx@Wc^T + bh+bc
    hgemm<1, 2048><<<dim3(8, 32), 128, SMEM>>>(
        hidcH, ctxH, nullptr, WhHp, WcHp, b1P, emb, nullptr, residH, EE);

    // 4) prediction = resid @ Wp^T + bp
    hgemm<2, 1024><<<dim3(8, 32), 128, SMEM>>>(
        residH, nullptr, nullptr, WpHp, nullptr, bp, nullptr, pred, nullptr, EE);
}